// round 2
// baseline (speedup 1.0000x reference)
#include <cuda_runtime.h>
#include <math.h>

// Problem dims (fixed)
#define Bb   8
#define Ee   1024
#define Ss   2000
#define Hh   16
#define HDd  64
#define Mm   10
#define MLPn 4096
#define SEG  200      // Ss / Mm
#define BH   128      // Bb * Hh
#define LNEPS 1e-5f
#define QKSCALE 0.35355339059327373f   // 64^-0.25

// ---------------- scratch (static device memory; no allocation allowed) ----
__device__ float g_XT  [(size_t)Bb*Ss*Ee];      // (B,S,E)
__device__ float g_Q   [(size_t)BH*Ss*HDd];     // (B,H,S,HD) scaled
__device__ float g_K   [(size_t)BH*Ss*HDd];     // scaled
__device__ float g_V   [(size_t)BH*Ss*HDd];
__device__ float g_Ql  [BH*Mm*HDd];
__device__ float g_Kl  [BH*Mm*HDd];
__device__ float g_k2  [BH*Mm*Mm];
__device__ float g_k2inv[BH*Mm*Mm];
__device__ float g_normv;
__device__ float g_k3V [BH*Mm*HDd];
__device__ float g_coeff[(size_t)BH*Ss*Mm];     // k1 @ inv(k2)
__device__ float g_attn[(size_t)Bb*Ss*Ee];      // (B,S,E)
__device__ float g_h1  [(size_t)Bb*Ss*Ee];
__device__ float g_mid [(size_t)Bb*Ss*MLPn];
__device__ float g_h2  [(size_t)Bb*Ss*Ee];

// ---------------- transpose in: X (B,E,S) -> g_XT (B,S,E) ------------------
__global__ void k_transpose_in(const float* __restrict__ X) {
    __shared__ float t[32][33];
    int b = blockIdx.z;
    int s0 = blockIdx.x * 32, e0 = blockIdx.y * 32;
    int tx = threadIdx.x, ty = threadIdx.y;
#pragma unroll
    for (int i = 0; i < 4; i++) {
        int e = e0 + ty + i * 8, s = s0 + tx;
        if (s < Ss) t[ty + i * 8][tx] = X[((size_t)b * Ee + e) * Ss + s];
    }
    __syncthreads();
#pragma unroll
    for (int i = 0; i < 4; i++) {
        int s = s0 + ty + i * 8, e = e0 + tx;
        if (s < Ss) g_XT[((size_t)b * Ss + s) * Ee + e] = t[tx][ty + i * 8];
    }
}

// ---------------- transpose out: g_h1 (B,S,E) -> out (B,E,S) ---------------
__global__ void k_transpose_out(float* __restrict__ out) {
    __shared__ float t[32][33];
    int b = blockIdx.z;
    int e0 = blockIdx.x * 32, s0 = blockIdx.y * 32;
    int tx = threadIdx.x, ty = threadIdx.y;
#pragma unroll
    for (int i = 0; i < 4; i++) {
        int s = s0 + ty + i * 8, e = e0 + tx;
        if (s < Ss) t[ty + i * 8][tx] = g_h1[((size_t)b * Ss + s) * Ee + e];
    }
    __syncthreads();
#pragma unroll
    for (int i = 0; i < 4; i++) {
        int e = e0 + ty + i * 8, s = s0 + tx;
        if (s < Ss) out[((size_t)b * Ee + e) * Ss + s] = t[tx][ty + i * 8];
    }
}

// ---------------- generic NT SGEMM: C = A(MxK) * W(NxK)^T + bias -----------
// mode 0: write (B,H,S,HD) layout, v = (acc+bias)*scale   (QKV projections)
// mode 1: row-major, exact GELU(acc+bias)                 (MLP1)
// mode 2: row-major, acc+bias                             (MLP2)
__global__ void __launch_bounds__(256) k_sgemm(
    const float* __restrict__ A, const float* __restrict__ W,
    const float* __restrict__ bias, float* __restrict__ C,
    int Kdim, int Ndim, int mode, float scale)
{
    __shared__ float As[16][64];
    __shared__ float Bs[16][64];
    int tid = threadIdx.x;
    int row0 = blockIdx.x * 64, col0 = blockIdx.y * 64;
    int lr = tid >> 2, lk = (tid & 3) << 2;
    const float* Ap = A + (size_t)(row0 + lr) * Kdim + lk;
    const float* Wp = W + (size_t)(col0 + lr) * Kdim + lk;
    int tx = tid & 15, ty = tid >> 4;
    float acc[4][4];
#pragma unroll
    for (int i = 0; i < 4; i++)
#pragma unroll
        for (int j = 0; j < 4; j++) acc[i][j] = 0.f;

    for (int k0 = 0; k0 < Kdim; k0 += 16) {
        float4 a4 = *(const float4*)(Ap + k0);
        float4 b4 = *(const float4*)(Wp + k0);
        As[lk + 0][lr] = a4.x; As[lk + 1][lr] = a4.y;
        As[lk + 2][lr] = a4.z; As[lk + 3][lr] = a4.w;
        Bs[lk + 0][lr] = b4.x; Bs[lk + 1][lr] = b4.y;
        Bs[lk + 2][lr] = b4.z; Bs[lk + 3][lr] = b4.w;
        __syncthreads();
#pragma unroll
        for (int kk = 0; kk < 16; kk++) {
            float4 av = *(const float4*)(&As[kk][ty << 2]);
            float4 bv = *(const float4*)(&Bs[kk][tx << 2]);
            float a[4] = {av.x, av.y, av.z, av.w};
            float b[4] = {bv.x, bv.y, bv.z, bv.w};
#pragma unroll
            for (int i = 0; i < 4; i++)
#pragma unroll
                for (int j = 0; j < 4; j++) acc[i][j] += a[i] * b[j];
        }
        __syncthreads();
    }

#pragma unroll
    for (int i = 0; i < 4; i++) {
        int r = row0 + (ty << 2) + i;
#pragma unroll
        for (int j = 0; j < 4; j++) {
            int c = col0 + (tx << 2) + j;
            float v = acc[i][j] + bias[c];
            if (mode == 0) {
                v *= scale;
                int bb = r / Ss, s = r % Ss, h = c >> 6, d = c & 63;
                C[(((size_t)(bb * Hh + h)) * Ss + s) * HDd + d] = v;
            } else {
                if (mode == 1) v = 0.5f * v * (1.f + erff(v * 0.7071067811865475f));
                C[(size_t)r * Ndim + c] = v;
            }
        }
    }
}

// ---------------- landmarks: segment means over 200 s ----------------------
__global__ void k_landmarks() {
    int bhm = blockIdx.x;
    int m = bhm % Mm, bh = bhm / Mm;
    int d = threadIdx.x;  // 64
    const float* Qb = g_Q + ((size_t)bh * Ss + m * SEG) * HDd + d;
    const float* Kb = g_K + ((size_t)bh * Ss + m * SEG) * HDd + d;
    float aq = 0.f, ak = 0.f;
    for (int j = 0; j < SEG; j++) { aq += Qb[(size_t)j * HDd]; ak += Kb[(size_t)j * HDd]; }
    g_Ql[(bh * Mm + m) * HDd + d] = aq * (1.f / SEG);
    g_Kl[(bh * Mm + m) * HDd + d] = ak * (1.f / SEG);
}

// ---------------- k2 = softmax(Ql @ Kl^T), per (b,h) -----------------------
__global__ void k_k2() {
    int bh = blockIdx.x;
    __shared__ float sQ[Mm * HDd], sK[Mm * HDd], sl[Mm][Mm];
    int t = threadIdx.x;  // 128
    for (int i = t; i < Mm * HDd; i += 128) {
        sQ[i] = g_Ql[bh * Mm * HDd + i];
        sK[i] = g_Kl[bh * Mm * HDd + i];
    }
    __syncthreads();
    if (t < 100) {
        int i = t / 10, j = t % 10;
        float s = 0.f;
#pragma unroll
        for (int d = 0; d < 64; d++) s += sQ[i * 64 + d] * sK[j * 64 + d];
        sl[i][j] = s;
    }
    __syncthreads();
    if (t < 100) {
        int i = t / 10, j = t % 10;
        float mx = -1e30f;
#pragma unroll
        for (int k = 0; k < 10; k++) mx = fmaxf(mx, sl[i][k]);
        float sum = 0.f;
#pragma unroll
        for (int k = 0; k < 10; k++) sum += expf(sl[i][k] - mx);
        g_k2[bh * 100 + t] = expf(sl[i][j] - mx) / sum;
    }
}

// ------- global normalization: max colsum(|k2|) * max rowsum(|k2|) --------
__global__ void k_norm() {
    __shared__ float rc[256], rr[256];
    int t = threadIdx.x;
    float mc = 0.f, mr = 0.f;
    for (int idx = t; idx < BH * Mm; idx += 256) {
        int bh = idx / Mm, j = idx % Mm;
        const float* Kp = g_k2 + bh * 100;
        float cs = 0.f, rs = 0.f;
#pragma unroll
        for (int i = 0; i < 10; i++) { cs += fabsf(Kp[i * 10 + j]); rs += fabsf(Kp[j * 10 + i]); }
        mc = fmaxf(mc, cs); mr = fmaxf(mr, rs);
    }
    rc[t] = mc; rr[t] = mr; __syncthreads();
    for (int o = 128; o > 0; o >>= 1) {
        if (t < o) { rc[t] = fmaxf(rc[t], rc[t + o]); rr[t] = fmaxf(rr[t], rr[t + o]); }
        __syncthreads();
    }
    if (t == 0) g_normv = rc[0] * rr[0];
}

// ---------------- Newton-Schulz iterative inverse of 10x10 k2 --------------
__global__ void k_inv() {
    int bh = blockIdx.x, t = threadIdx.x;  // 128 threads
    __shared__ float sK[100], sV[100], sKV[100], sA[100], sB2[100];
    if (t < 100) sK[t] = g_k2[bh * 100 + t];
    __syncthreads();
    float denom = g_normv;
    int i = t / 10, j = t % 10;
    if (t < 100) sV[t] = sK[j * 10 + i] / denom;
    __syncthreads();
    for (int it = 0; it < 6; it++) {
        if (t < 100) { float s = 0.f;
#pragma unroll
            for (int k = 0; k < 10; k++) s += sK[i * 10 + k] * sV[k * 10 + j];
            sKV[t] = s; }
        __syncthreads();
        if (t < 100) sA[t] = (i == j ? 7.f : 0.f) - sKV[t];               // T1
        __syncthreads();
        if (t < 100) { float s = 0.f;
#pragma unroll
            for (int k = 0; k < 10; k++) s += sKV[i * 10 + k] * sA[k * 10 + j];
            sB2[t] = (i == j ? 15.f : 0.f) - s; }                          // T2
        __syncthreads();
        if (t < 100) { float s = 0.f;
#pragma unroll
            for (int k = 0; k < 10; k++) s += sKV[i * 10 + k] * sB2[k * 10 + j];
            sA[t] = (i == j ? 13.f : 0.f) - s; }                           // T3
        __syncthreads();
        if (t < 100) { float s = 0.f;
#pragma unroll
            for (int k = 0; k < 10; k++) s += sV[i * 10 + k] * sA[k * 10 + j];
            sB2[t] = 0.25f * s; }
        __syncthreads();
        if (t < 100) sV[t] = sB2[t];
        __syncthreads();
    }
    if (t < 100) g_k2inv[bh * 100 + t] = sV[t];
}

// -------- fused k3 softmax (over S) @ V -> g_k3V (B,H,M,HD) ----------------
__global__ void k_k3v() {
    int bm = blockIdx.x;
    int m = bm % Mm, bh = bm / Mm;
    __shared__ float sq[64];
    __shared__ float sl[Ss];
    __shared__ float red[256];
    __shared__ float sout[4][64];
    int t = threadIdx.x, lane = t & 31, w = t >> 5;
    if (t < 64) sq[t] = g_Ql[(bh * Mm + m) * 64 + t];
    __syncthreads();
    for (int s = w; s < Ss; s += 8) {
        const float* Kr = g_K + ((size_t)bh * Ss + s) * 64;
        float p = sq[lane] * Kr[lane] + sq[lane + 32] * Kr[lane + 32];
#pragma unroll
        for (int o = 16; o; o >>= 1) p += __shfl_xor_sync(0xffffffffu, p, o);
        if (lane == 0) sl[s] = p;
    }
    __syncthreads();
    float mx = -1e30f;
    for (int s = t; s < Ss; s += 256) mx = fmaxf(mx, sl[s]);
    red[t] = mx; __syncthreads();
    for (int o = 128; o; o >>= 1) { if (t < o) red[t] = fmaxf(red[t], red[t + o]); __syncthreads(); }
    mx = red[0]; __syncthreads();
    float sm = 0.f;
    for (int s = t; s < Ss; s += 256) { float e = expf(sl[s] - mx); sl[s] = e; sm += e; }
    red[t] = sm; __syncthreads();
    for (int o = 128; o; o >>= 1) { if (t < o) red[t] += red[t + o]; __syncthreads(); }
    float inv = 1.f / red[0];
    int g = t >> 6, d = t & 63;
    float acc = 0.f;
    for (int s = g; s < Ss; s += 4) acc += sl[s] * g_V[((size_t)bh * Ss + s) * 64 + d];
    sout[g][d] = acc; __syncthreads();
    if (t < 64)
        g_k3V[(bh * Mm + m) * 64 + t] =
            (sout[0][t] + sout[1][t] + sout[2][t] + sout[3][t]) * inv;
}

// -------- coeff = softmax(Q @ Kl^T) @ inv(k2), per s -----------------------
__global__ void k_coeff() {
    int bh = blockIdx.x, t = threadIdx.x, lane = t & 31, w = t >> 5;
    __shared__ float sKl[Mm][64];
    __shared__ float sInv[100];
    for (int i = t; i < Mm * 64; i += 256) sKl[i / 64][i % 64] = g_Kl[bh * Mm * 64 + i];
    if (t < 100) sInv[t] = g_k2inv[bh * 100 + t];
    __syncthreads();
    for (int s = w; s < Ss; s += 8) {
        const float* Qr = g_Q + ((size_t)bh * Ss + s) * 64;
        float qa = Qr[lane], qb = Qr[lane + 32];
        float lg[10];
#pragma unroll
        for (int mm = 0; mm < 10; mm++) {
            float p = qa * sKl[mm][lane] + qb * sKl[mm][lane + 32];
#pragma unroll
            for (int o = 16; o; o >>= 1) p += __shfl_xor_sync(0xffffffffu, p, o);
            lg[mm] = p;
        }
        float mx = lg[0];
#pragma unroll
        for (int mm = 1; mm < 10; mm++) mx = fmaxf(mx, lg[mm]);
        float sum = 0.f;
#pragma unroll
        for (int mm = 0; mm < 10; mm++) { lg[mm] = expf(lg[mm] - mx); sum += lg[mm]; }
        float is = 1.f / sum;
        if (lane < 10) {
            float c = 0.f;
#pragma unroll
            for (int mm = 0; mm < 10; mm++) c += lg[mm] * sInv[mm * 10 + lane];
            g_coeff[((size_t)bh * Ss + s) * Mm + lane] = c * is;
        }
    }
}

// -------- attn[b,s,h*64+d] = coeff[s,:] @ k3V ------------------------------
__global__ void k_attn() {
    int bh = blockIdx.x;
    int s0 = blockIdx.y * 50;
    int b = bh / Hh, h = bh % Hh;
    __shared__ float sc[50][10];
    __shared__ float sw[10][64];
    int t = threadIdx.x;
    for (int i = t; i < 500; i += 256) sc[i / 10][i % 10] = g_coeff[((size_t)bh * Ss + s0) * Mm + i];
    for (int i = t; i < 640; i += 256) sw[i / 64][i % 64] = g_k3V[bh * Mm * 64 + i];
    __syncthreads();
    int d = t & 63, si0 = t >> 6;
    for (int si = si0; si < 50; si += 4) {
        float v = 0.f;
#pragma unroll
        for (int n = 0; n < 10; n++) v += sc[si][n] * sw[n][d];
        g_attn[((size_t)(b * Ss + s0 + si)) * Ee + h * 64 + d] = v;
    }
}

// -------- layernorm over last dim (E=1024), row per block ------------------
__global__ void k_ln(const float* __restrict__ x, const float* __restrict__ g,
                     const float* __restrict__ be, float* __restrict__ y) {
    int row = blockIdx.x, t = threadIdx.x;
    const float* xr = x + (size_t)row * Ee;
    __shared__ float r1[256], r2[256];
    float s = 0.f, ss = 0.f;
    for (int e = t; e < Ee; e += 256) { float v = xr[e]; s += v; ss += v * v; }
    r1[t] = s; r2[t] = ss; __syncthreads();
    for (int o = 128; o; o >>= 1) {
        if (t < o) { r1[t] += r1[t + o]; r2[t] += r2[t + o]; }
        __syncthreads();
    }
    float mu = r1[0] * (1.f / Ee);
    float var = r2[0] * (1.f / Ee) - mu * mu;
    float rstd = rsqrtf(var + LNEPS);
    for (int e = t; e < Ee; e += 256) {
        float v = xr[e];
        y[(size_t)row * Ee + e] = (v - mu) * rstd * g[e] + be[e];
    }
}

// ---------------------------------------------------------------------------
extern "C" void kernel_launch(void* const* d_in, const int* in_sizes, int n_in,
                              void* d_out, int out_size) {
    (void)in_sizes; (void)n_in; (void)out_size;
    const float* X   = (const float*)d_in[0];
    const float* Wq  = (const float*)d_in[1];
    const float* bq  = (const float*)d_in[2];
    const float* Wk  = (const float*)d_in[3];
    const float* bk  = (const float*)d_in[4];
    const float* Wv  = (const float*)d_in[5];
    const float* bv  = (const float*)d_in[6];
    const float* g1  = (const float*)d_in[7];
    const float* be1 = (const float*)d_in[8];
    const float* W1  = (const float*)d_in[9];
    const float* b1  = (const float*)d_in[10];
    const float* W2  = (const float*)d_in[11];
    const float* b2  = (const float*)d_in[12];
    const float* g2  = (const float*)d_in[13];
    const float* be2 = (const float*)d_in[14];
    float* out = (float*)d_out;

    float *pXT, *pQ, *pK, *pV, *pAttn, *pH1, *pMid, *pH2;
    cudaGetSymbolAddress((void**)&pXT,  g_XT);
    cudaGetSymbolAddress((void**)&pQ,   g_Q);
    cudaGetSymbolAddress((void**)&pK,   g_K);
    cudaGetSymbolAddress((void**)&pV,   g_V);
    cudaGetSymbolAddress((void**)&pAttn,g_attn);
    cudaGetSymbolAddress((void**)&pH1,  g_h1);
    cudaGetSymbolAddress((void**)&pMid, g_mid);
    cudaGetSymbolAddress((void**)&pH2,  g_h2);

    dim3 tb32(32, 8);
    // 1. X (B,E,S) -> XT (B,S,E)
    k_transpose_in<<<dim3((Ss + 31) / 32, Ee / 32, Bb), tb32>>>(X);
    // 2. QKV projections (NT GEMMs, M=16000, N=1024, K=1024)
    k_sgemm<<<dim3(250, 16), 256>>>(pXT, Wq, bq, pQ, Ee, Hh * HDd, 0, QKSCALE);
    k_sgemm<<<dim3(250, 16), 256>>>(pXT, Wk, bk, pK, Ee, Hh * HDd, 0, QKSCALE);
    k_sgemm<<<dim3(250, 16), 256>>>(pXT, Wv, bv, pV, Ee, Hh * HDd, 0, 1.0f);
    // 3. landmarks
    k_landmarks<<<BH * Mm, 64>>>();
    // 4. k2 softmax
    k_k2<<<BH, 128>>>();
    // 5. global normalization scalar
    k_norm<<<1, 256>>>();
    // 6. 10x10 Newton inverse per (b,h)
    k_inv<<<BH, 128>>>();
    // 7. fused k3-softmax @ V
    k_k3v<<<BH * Mm, 256>>>();
    // 8. coeff = softmax(Q Kl^T) @ inv
    k_coeff<<<BH, 256>>>();
    // 9. attn assembly -> (B,S,E)
    k_attn<<<dim3(BH, Ss / 50), 256>>>();
    // 10. LN1
    k_ln<<<Bb * Ss, 256>>>(pAttn, g1, be1, pH1);
    // 11. MLP1 + exact GELU (M=16000, N=4096, K=1024)
    k_sgemm<<<dim3(250, 64), 256>>>(pH1, W1, b1, pMid, Ee, MLPn, 1, 1.0f);
    // 12. MLP2 (M=16000, N=1024, K=4096)
    k_sgemm<<<dim3(250, 16), 256>>>(pMid, W2, b2, pH2, MLPn, Ee, 2, 1.0f);
    // 13. LN2 -> g_h1 (reuse)
    k_ln<<<Bb * Ss, 256>>>(pH2, g2, be2, pH1);
    // 14. (B,S,E) -> out (B,E,S)
    k_transpose_out<<<dim3(Ee / 32, (Ss + 31) / 32, Bb), tb32>>>(out);
}

// round 3
// speedup vs baseline: 2.5420x; 2.5420x over previous
#include <cuda_runtime.h>
#include <math.h>
#include <stdint.h>

// Problem dims (fixed)
#define Bb   8
#define Ee   1024
#define Ss   2000
#define Hh   16
#define HDd  64
#define Mm   10
#define MLPn 4096
#define SEG  200      // Ss / Mm
#define BH   128      // Bb * Hh
#define LNEPS 1e-5f
#define QKSCALE 0.35355339059327373f   // 64^-0.25

// ---------------- scratch (static device memory; no allocation allowed) ----
__device__ float g_XT  [(size_t)Bb*Ss*Ee];      // (B,S,E)
__device__ float g_Q   [(size_t)BH*Ss*HDd];     // (B,H,S,HD) scaled
__device__ float g_K   [(size_t)BH*Ss*HDd];     // scaled
__device__ float g_V   [(size_t)BH*Ss*HDd];
__device__ float g_Ql  [BH*Mm*HDd];
__device__ float g_Kl  [BH*Mm*HDd];
__device__ float g_k2  [BH*Mm*Mm];
__device__ float g_k2inv[BH*Mm*Mm];
__device__ float g_normv;
__device__ float g_k3V [BH*Mm*HDd];
__device__ float g_coeff[(size_t)BH*Ss*Mm];     // k1 @ inv(k2)
__device__ float g_attn[(size_t)Bb*Ss*Ee];      // (B,S,E)
__device__ float g_h1  [(size_t)Bb*Ss*Ee];
__device__ float g_mid [(size_t)Bb*Ss*MLPn];
__device__ float g_h2  [(size_t)Bb*Ss*Ee];

// ---------------- transpose in: X (B,E,S) -> g_XT (B,S,E) ------------------
__global__ void k_transpose_in(const float* __restrict__ X) {
    __shared__ float t[32][33];
    int b = blockIdx.z;
    int s0 = blockIdx.x * 32, e0 = blockIdx.y * 32;
    int tx = threadIdx.x, ty = threadIdx.y;
#pragma unroll
    for (int i = 0; i < 4; i++) {
        int e = e0 + ty + i * 8, s = s0 + tx;
        if (s < Ss) t[ty + i * 8][tx] = X[((size_t)b * Ee + e) * Ss + s];
    }
    __syncthreads();
#pragma unroll
    for (int i = 0; i < 4; i++) {
        int s = s0 + ty + i * 8, e = e0 + tx;
        if (s < Ss) g_XT[((size_t)b * Ss + s) * Ee + e] = t[tx][ty + i * 8];
    }
}

// ---------------- transpose out: g_h1 (B,S,E) -> out (B,E,S) ---------------
__global__ void k_transpose_out(float* __restrict__ out) {
    __shared__ float t[32][33];
    int b = blockIdx.z;
    int e0 = blockIdx.x * 32, s0 = blockIdx.y * 32;
    int tx = threadIdx.x, ty = threadIdx.y;
#pragma unroll
    for (int i = 0; i < 4; i++) {
        int s = s0 + ty + i * 8, e = e0 + tx;
        if (s < Ss) t[ty + i * 8][tx] = g_h1[((size_t)b * Ss + s) * Ee + e];
    }
    __syncthreads();
#pragma unroll
    for (int i = 0; i < 4; i++) {
        int e = e0 + ty + i * 8, s = s0 + tx;
        if (s < Ss) out[((size_t)b * Ee + e) * Ss + s] = t[tx][ty + i * 8];
    }
}

// ===================== TF32 tensor-core NT GEMM ============================
// C = A(MxK) * W(NxK)^T + bias, tf32 mma.sync, fp32 accumulate.
// BM=128, BN=128, BK=32. 256 threads = 8 warps in 2(row)x4(col) grid,
// each warp computes 64x32 via 4x4 grid of m16n8k8 fragments.
// Shared memory holds tiles pre-arranged in FRAGMENT order:
//   As[kstep(4)][mfrag(8)][lane(32)][4]  -> LDS.128 per A fragment
//   Bs[kstep(4)][nfrag(16)][lane(32)][2] -> LDS.64  per B fragment
// mode 0: (B,H,S,HD) scatter, *scale (QKV)   mode 1: GELU   mode 2: plain
#define TGEMM_SMEM (2 * (4096 + 4096) * 4)   // 64 KB (double buffered)

__device__ __forceinline__ uint32_t f2tf32(float f) {
    uint32_t u;
    asm("cvt.rna.tf32.f32 %0, %1;" : "=r"(u) : "f"(f));
    return u;
}

__global__ void __launch_bounds__(256) k_tgemm(
    const float* __restrict__ A, const float* __restrict__ W,
    const float* __restrict__ bias, float* __restrict__ C,
    int Kdim, int Ndim, int mode, float scale)
{
    extern __shared__ uint32_t sm[];
    uint32_t* As = sm;             // [2][4096]
    uint32_t* Bs = sm + 2 * 4096;  // [2][4096]

    const int tid = threadIdx.x;
    const int lane = tid & 31, warp = tid >> 5;
    const int warpRow = warp >> 2, warpCol = warp & 3;
    const int g = lane >> 2, t4 = lane & 3;
    const size_t row0 = (size_t)blockIdx.x * 128;
    const size_t col0 = (size_t)blockIdx.y * 128;

    // loader per-thread geometry: 4 float4 loads, id = tid + i*256
    int lrow[4], lcol4[4], aoff[4], boff[4];
#pragma unroll
    for (int i = 0; i < 4; i++) {
        int id = tid + i * 256;
        int row = id >> 3, c4 = id & 7;
        lrow[i] = row; lcol4[i] = c4;
        int kstep = c4 >> 1, idx = c4 & 1;
        // A: [kstep][mfrag=row>>4][lane'=(row&7)*4 + j][4] elem ((row>>3)&1)+2*idx, j adds 4
        aoff[i] = ((kstep * 8 + (row >> 4)) * 32 + (row & 7) * 4) * 4
                  + ((row >> 3) & 1) + 2 * idx;
        // B: [kstep][nfrag=row>>3][lane'=(row&7)*4 + j][2] elem idx, j adds 2
        boff[i] = ((kstep * 16 + (row >> 3)) * 32 + (row & 7) * 4) * 2 + idx;
    }

    float acc[4][4][4];
#pragma unroll
    for (int mf = 0; mf < 4; mf++)
#pragma unroll
        for (int nf = 0; nf < 4; nf++)
#pragma unroll
            for (int r = 0; r < 4; r++) acc[mf][nf][r] = 0.f;

    const int KT = Kdim >> 5;
    float4 ra[4], rb[4];

    // prologue: load K-tile 0
#pragma unroll
    for (int i = 0; i < 4; i++) {
        ra[i] = *(const float4*)(A + (row0 + lrow[i]) * Kdim + lcol4[i] * 4);
        rb[i] = *(const float4*)(W + (col0 + lrow[i]) * Kdim + lcol4[i] * 4);
    }
#pragma unroll
    for (int i = 0; i < 4; i++) {
        uint32_t* ap = As + aoff[i];
        ap[0]  = f2tf32(ra[i].x); ap[4]  = f2tf32(ra[i].y);
        ap[8]  = f2tf32(ra[i].z); ap[12] = f2tf32(ra[i].w);
        uint32_t* bp = Bs + boff[i];
        bp[0] = f2tf32(rb[i].x); bp[2] = f2tf32(rb[i].y);
        bp[4] = f2tf32(rb[i].z); bp[6] = f2tf32(rb[i].w);
    }
    __syncthreads();

    for (int kt = 0; kt < KT; kt++) {
        const int cur = kt & 1, nxt = cur ^ 1;
        const bool more = (kt + 1 < KT);
        if (more) {
            const float* Ap = A + (size_t)(kt + 1) * 32;
            const float* Wp = W + (size_t)(kt + 1) * 32;
#pragma unroll
            for (int i = 0; i < 4; i++) {
                ra[i] = *(const float4*)(Ap + (row0 + lrow[i]) * Kdim + lcol4[i] * 4);
                rb[i] = *(const float4*)(Wp + (col0 + lrow[i]) * Kdim + lcol4[i] * 4);
            }
        }
        const uint32_t* Ab = As + cur * 4096;
        const uint32_t* Bbuf = Bs + cur * 4096;
#pragma unroll
        for (int ks = 0; ks < 4; ks++) {
            uint4 af[4]; uint2 bf[4];
#pragma unroll
            for (int mf = 0; mf < 4; mf++)
                af[mf] = *(const uint4*)(Ab + ((ks * 8 + warpRow * 4 + mf) * 32 + lane) * 4);
#pragma unroll
            for (int nf = 0; nf < 4; nf++)
                bf[nf] = *(const uint2*)(Bbuf + ((ks * 16 + warpCol * 4 + nf) * 32 + lane) * 2);
#pragma unroll
            for (int mf = 0; mf < 4; mf++)
#pragma unroll
                for (int nf = 0; nf < 4; nf++) {
                    asm volatile(
                        "mma.sync.aligned.m16n8k8.row.col.f32.tf32.tf32.f32 "
                        "{%0,%1,%2,%3},{%4,%5,%6,%7},{%8,%9},{%0,%1,%2,%3};"
                        : "+f"(acc[mf][nf][0]), "+f"(acc[mf][nf][1]),
                          "+f"(acc[mf][nf][2]), "+f"(acc[mf][nf][3])
                        : "r"(af[mf].x), "r"(af[mf].y), "r"(af[mf].z), "r"(af[mf].w),
                          "r"(bf[nf].x), "r"(bf[nf].y));
                }
        }
        if (more) {
            uint32_t* Aw = As + nxt * 4096;
            uint32_t* Bw = Bs + nxt * 4096;
#pragma unroll
            for (int i = 0; i < 4; i++) {
                uint32_t* ap = Aw + aoff[i];
                ap[0]  = f2tf32(ra[i].x); ap[4]  = f2tf32(ra[i].y);
                ap[8]  = f2tf32(ra[i].z); ap[12] = f2tf32(ra[i].w);
                uint32_t* bp = Bw + boff[i];
                bp[0] = f2tf32(rb[i].x); bp[2] = f2tf32(rb[i].y);
                bp[4] = f2tf32(rb[i].z); bp[6] = f2tf32(rb[i].w);
            }
        }
        __syncthreads();
    }

    // ---- epilogue ----
#pragma unroll
    for (int mf = 0; mf < 4; mf++) {
#pragma unroll
        for (int h2 = 0; h2 < 2; h2++) {
            const size_t r = row0 + warpRow * 64 + mf * 16 + g + h2 * 8;
#pragma unroll
            for (int nf = 0; nf < 4; nf++) {
                const int c = (int)col0 + warpCol * 32 + nf * 8 + t4 * 2;
                float v0 = acc[mf][nf][h2 * 2 + 0] + bias[c];
                float v1 = acc[mf][nf][h2 * 2 + 1] + bias[c + 1];
                if (mode == 0) {
                    v0 *= scale; v1 *= scale;
                    int bb = (int)(r / Ss), s = (int)(r % Ss);
                    int h = c >> 6, d = c & 63;
                    float2* dst = (float2*)&C[(((size_t)(bb * Hh + h)) * Ss + s) * HDd + d];
                    *dst = make_float2(v0, v1);
                } else {
                    if (mode == 1) {
                        v0 = 0.5f * v0 * (1.f + erff(v0 * 0.7071067811865475f));
                        v1 = 0.5f * v1 * (1.f + erff(v1 * 0.7071067811865475f));
                    }
                    float2* dst = (float2*)&C[r * Ndim + c];
                    *dst = make_float2(v0, v1);
                }
            }
        }
    }
}

// ---------------- landmarks: segment means over 200 s ----------------------
__global__ void k_landmarks() {
    int bhm = blockIdx.x;
    int m = bhm % Mm, bh = bhm / Mm;
    int d = threadIdx.x;  // 64
    const float* Qb = g_Q + ((size_t)bh * Ss + m * SEG) * HDd + d;
    const float* Kb = g_K + ((size_t)bh * Ss + m * SEG) * HDd + d;
    float aq = 0.f, ak = 0.f;
    for (int j = 0; j < SEG; j++) { aq += Qb[(size_t)j * HDd]; ak += Kb[(size_t)j * HDd]; }
    g_Ql[(bh * Mm + m) * HDd + d] = aq * (1.f / SEG);
    g_Kl[(bh * Mm + m) * HDd + d] = ak * (1.f / SEG);
}

// ---------------- k2 = softmax(Ql @ Kl^T), per (b,h) -----------------------
__global__ void k_k2() {
    int bh = blockIdx.x;
    __shared__ float sQ[Mm * HDd], sK[Mm * HDd], sl[Mm][Mm];
    int t = threadIdx.x;  // 128
    for (int i = t; i < Mm * HDd; i += 128) {
        sQ[i] = g_Ql[bh * Mm * HDd + i];
        sK[i] = g_Kl[bh * Mm * HDd + i];
    }
    __syncthreads();
    if (t < 100) {
        int i = t / 10, j = t % 10;
        float s = 0.f;
#pragma unroll
        for (int d = 0; d < 64; d++) s += sQ[i * 64 + d] * sK[j * 64 + d];
        sl[i][j] = s;
    }
    __syncthreads();
    if (t < 100) {
        int i = t / 10, j = t % 10;
        float mx = -1e30f;
#pragma unroll
        for (int k = 0; k < 10; k++) mx = fmaxf(mx, sl[i][k]);
        float sum = 0.f;
#pragma unroll
        for (int k = 0; k < 10; k++) sum += expf(sl[i][k] - mx);
        g_k2[bh * 100 + t] = expf(sl[i][j] - mx) / sum;
    }
}

// ------- global normalization: max colsum(|k2|) * max rowsum(|k2|) --------
__global__ void k_norm() {
    __shared__ float rc[256], rr[256];
    int t = threadIdx.x;
    float mc = 0.f, mr = 0.f;
    for (int idx = t; idx < BH * Mm; idx += 256) {
        int bh = idx / Mm, j = idx % Mm;
        const float* Kp = g_k2 + bh * 100;
        float cs = 0.f, rs = 0.f;
#pragma unroll
        for (int i = 0; i < 10; i++) { cs += fabsf(Kp[i * 10 + j]); rs += fabsf(Kp[j * 10 + i]); }
        mc = fmaxf(mc, cs); mr = fmaxf(mr, rs);
    }
    rc[t] = mc; rr[t] = mr; __syncthreads();
    for (int o = 128; o > 0; o >>= 1) {
        if (t < o) { rc[t] = fmaxf(rc[t], rc[t + o]); rr[t] = fmaxf(rr[t], rr[t + o]); }
        __syncthreads();
    }
    if (t == 0) g_normv = rc[0] * rr[0];
}

// ---------------- Newton-Schulz iterative inverse of 10x10 k2 --------------
__global__ void k_inv() {
    int bh = blockIdx.x, t = threadIdx.x;  // 128 threads
    __shared__ float sK[100], sV[100], sKV[100], sA[100], sB2[100];
    if (t < 100) sK[t] = g_k2[bh * 100 + t];
    __syncthreads();
    float denom = g_normv;
    int i = t / 10, j = t % 10;
    if (t < 100) sV[t] = sK[j * 10 + i] / denom;
    __syncthreads();
    for (int it = 0; it < 6; it++) {
        if (t < 100) { float s = 0.f;
#pragma unroll
            for (int k = 0; k < 10; k++) s += sK[i * 10 + k] * sV[k * 10 + j];
            sKV[t] = s; }
        __syncthreads();
        if (t < 100) sA[t] = (i == j ? 7.f : 0.f) - sKV[t];
        __syncthreads();
        if (t < 100) { float s = 0.f;
#pragma unroll
            for (int k = 0; k < 10; k++) s += sKV[i * 10 + k] * sA[k * 10 + j];
            sB2[t] = (i == j ? 15.f : 0.f) - s; }
        __syncthreads();
        if (t < 100) { float s = 0.f;
#pragma unroll
            for (int k = 0; k < 10; k++) s += sKV[i * 10 + k] * sB2[k * 10 + j];
            sA[t] = (i == j ? 13.f : 0.f) - s; }
        __syncthreads();
        if (t < 100) { float s = 0.f;
#pragma unroll
            for (int k = 0; k < 10; k++) s += sV[i * 10 + k] * sA[k * 10 + j];
            sB2[t] = 0.25f * s; }
        __syncthreads();
        if (t < 100) sV[t] = sB2[t];
        __syncthreads();
    }
    if (t < 100) g_k2inv[bh * 100 + t] = sV[t];
}

// -------- fused k3 softmax (over S) @ V -> g_k3V (B,H,M,HD) ----------------
__global__ void k_k3v() {
    int bm = blockIdx.x;
    int m = bm % Mm, bh = bm / Mm;
    __shared__ float sq[64];
    __shared__ float sl[Ss];
    __shared__ float red[256];
    __shared__ float sout[4][64];
    int t = threadIdx.x, lane = t & 31, w = t >> 5;
    if (t < 64) sq[t] = g_Ql[(bh * Mm + m) * 64 + t];
    __syncthreads();
    for (int s = w; s < Ss; s += 8) {
        const float* Kr = g_K + ((size_t)bh * Ss + s) * 64;
        float p = sq[lane] * Kr[lane] + sq[lane + 32] * Kr[lane + 32];
#pragma unroll
        for (int o = 16; o; o >>= 1) p += __shfl_xor_sync(0xffffffffu, p, o);
        if (lane == 0) sl[s] = p;
    }
    __syncthreads();
    float mx = -1e30f;
    for (int s = t; s < Ss; s += 256) mx = fmaxf(mx, sl[s]);
    red[t] = mx; __syncthreads();
    for (int o = 128; o; o >>= 1) { if (t < o) red[t] = fmaxf(red[t], red[t + o]); __syncthreads(); }
    mx = red[0]; __syncthreads();
    float sm = 0.f;
    for (int s = t; s < Ss; s += 256) { float e = expf(sl[s] - mx); sl[s] = e; sm += e; }
    red[t] = sm; __syncthreads();
    for (int o = 128; o; o >>= 1) { if (t < o) red[t] += red[t + o]; __syncthreads(); }
    float inv = 1.f / red[0];
    int gg = t >> 6, d = t & 63;
    float acc = 0.f;
    for (int s = gg; s < Ss; s += 4) acc += sl[s] * g_V[((size_t)bh * Ss + s) * 64 + d];
    sout[gg][d] = acc; __syncthreads();
    if (t < 64)
        g_k3V[(bh * Mm + m) * 64 + t] =
            (sout[0][t] + sout[1][t] + sout[2][t] + sout[3][t]) * inv;
}

// -------- coeff = softmax(Q @ Kl^T) @ inv(k2), per s -----------------------
__global__ void k_coeff() {
    int bh = blockIdx.x, t = threadIdx.x, lane = t & 31, w = t >> 5;
    __shared__ float sKl[Mm][64];
    __shared__ float sInv[100];
    for (int i = t; i < Mm * 64; i += 256) sKl[i / 64][i % 64] = g_Kl[bh * Mm * 64 + i];
    if (t < 100) sInv[t] = g_k2inv[bh * 100 + t];
    __syncthreads();
    for (int s = w; s < Ss; s += 8) {
        const float* Qr = g_Q + ((size_t)bh * Ss + s) * 64;
        float qa = Qr[lane], qb = Qr[lane + 32];
        float lg[10];
#pragma unroll
        for (int mm = 0; mm < 10; mm++) {
            float p = qa * sKl[mm][lane] + qb * sKl[mm][lane + 32];
#pragma unroll
            for (int o = 16; o; o >>= 1) p += __shfl_xor_sync(0xffffffffu, p, o);
            lg[mm] = p;
        }
        float mx = lg[0];
#pragma unroll
        for (int mm = 1; mm < 10; mm++) mx = fmaxf(mx, lg[mm]);
        float sum = 0.f;
#pragma unroll
        for (int mm = 0; mm < 10; mm++) { lg[mm] = expf(lg[mm] - mx); sum += lg[mm]; }
        float is = 1.f / sum;
        if (lane < 10) {
            float c = 0.f;
#pragma unroll
            for (int mm = 0; mm < 10; mm++) c += lg[mm] * sInv[mm * 10 + lane];
            g_coeff[((size_t)bh * Ss + s) * Mm + lane] = c * is;
        }
    }
}

// -------- attn[b,s,h*64+d] = coeff[s,:] @ k3V ------------------------------
__global__ void k_attn() {
    int bh = blockIdx.x;
    int s0 = blockIdx.y * 50;
    int b = bh / Hh, h = bh % Hh;
    __shared__ float sc[50][10];
    __shared__ float sw[10][64];
    int t = threadIdx.x;
    for (int i = t; i < 500; i += 256) sc[i / 10][i % 10] = g_coeff[((size_t)bh * Ss + s0) * Mm + i];
    for (int i = t; i < 640; i += 256) sw[i / 64][i % 64] = g_k3V[bh * Mm * 64 + i];
    __syncthreads();
    int d = t & 63, si0 = t >> 6;
    for (int si = si0; si < 50; si += 4) {
        float v = 0.f;
#pragma unroll
        for (int n = 0; n < 10; n++) v += sc[si][n] * sw[n][d];
        g_attn[((size_t)(b * Ss + s0 + si)) * Ee + h * 64 + d] = v;
    }
}

// -------- layernorm over last dim (E=1024), row per block ------------------
__global__ void k_ln(const float* __restrict__ x, const float* __restrict__ g,
                     const float* __restrict__ be, float* __restrict__ y) {
    int row = blockIdx.x, t = threadIdx.x;
    const float* xr = x + (size_t)row * Ee;
    __shared__ float r1[256], r2[256];
    float s = 0.f, ss = 0.f;
    for (int e = t; e < Ee; e += 256) { float v = xr[e]; s += v; ss += v * v; }
    r1[t] = s; r2[t] = ss; __syncthreads();
    for (int o = 128; o; o >>= 1) {
        if (t < o) { r1[t] += r1[t + o]; r2[t] += r2[t + o]; }
        __syncthreads();
    }
    float mu = r1[0] * (1.f / Ee);
    float var = r2[0] * (1.f / Ee) - mu * mu;
    float rstd = rsqrtf(var + LNEPS);
    for (int e = t; e < Ee; e += 256) {
        float v = xr[e];
        y[(size_t)row * Ee + e] = (v - mu) * rstd * g[e] + be[e];
    }
}

// ---------------------------------------------------------------------------
extern "C" void kernel_launch(void* const* d_in, const int* in_sizes, int n_in,
                              void* d_out, int out_size) {
    (void)in_sizes; (void)n_in; (void)out_size;
    const float* X   = (const float*)d_in[0];
    const float* Wq  = (const float*)d_in[1];
    const float* bq  = (const float*)d_in[2];
    const float* Wk  = (const float*)d_in[3];
    const float* bk  = (const float*)d_in[4];
    const float* Wv  = (const float*)d_in[5];
    const float* bv  = (const float*)d_in[6];
    const float* g1  = (const float*)d_in[7];
    const float* be1 = (const float*)d_in[8];
    const float* W1  = (const float*)d_in[9];
    const float* b1  = (const float*)d_in[10];
    const float* W2  = (const float*)d_in[11];
    const float* b2  = (const float*)d_in[12];
    const float* g2  = (const float*)d_in[13];
    const float* be2 = (const float*)d_in[14];
    float* out = (float*)d_out;

    float *pXT, *pQ, *pK, *pV, *pAttn, *pH1, *pMid, *pH2;
    cudaGetSymbolAddress((void**)&pXT,  g_XT);
    cudaGetSymbolAddress((void**)&pQ,   g_Q);
    cudaGetSymbolAddress((void**)&pK,   g_K);
    cudaGetSymbolAddress((void**)&pV,   g_V);
    cudaGetSymbolAddress((void**)&pAttn,g_attn);
    cudaGetSymbolAddress((void**)&pH1,  g_h1);
    cudaGetSymbolAddress((void**)&pMid, g_mid);
    cudaGetSymbolAddress((void**)&pH2,  g_h2);

    static int smem_set = 0;
    if (!smem_set) {
        cudaFuncSetAttribute(k_tgemm, cudaFuncAttributeMaxDynamicSharedMemorySize,
                             TGEMM_SMEM);
        smem_set = 1;
    }

    dim3 tb32(32, 8);
    // 1. X (B,E,S) -> XT (B,S,E)
    k_transpose_in<<<dim3((Ss + 31) / 32, Ee / 32, Bb), tb32>>>(X);
    // 2. QKV projections (tf32 tensor GEMM, M=16000, N=1024, K=1024)
    k_tgemm<<<dim3(125, 8), 256, TGEMM_SMEM>>>(pXT, Wq, bq, pQ, Ee, Hh * HDd, 0, QKSCALE);
    k_tgemm<<<dim3(125, 8), 256, TGEMM_SMEM>>>(pXT, Wk, bk, pK, Ee, Hh * HDd, 0, QKSCALE);
    k_tgemm<<<dim3(125, 8), 256, TGEMM_SMEM>>>(pXT, Wv, bv, pV, Ee, Hh * HDd, 0, 1.0f);
    // 3. landmarks
    k_landmarks<<<BH * Mm, 64>>>();
    // 4. k2 softmax
    k_k2<<<BH, 128>>>();
    // 5. global normalization scalar
    k_norm<<<1, 256>>>();
    // 6. 10x10 Newton inverse per (b,h)
    k_inv<<<BH, 128>>>();
    // 7. fused k3-softmax @ V
    k_k3v<<<BH * Mm, 256>>>();
    // 8. coeff = softmax(Q Kl^T) @ inv
    k_coeff<<<BH, 256>>>();
    // 9. attn assembly -> (B,S,E)
    k_attn<<<dim3(BH, Ss / 50), 256>>>();
    // 10. LN1
    k_ln<<<Bb * Ss, 256>>>(pAttn, g1, be1, pH1);
    // 11. MLP1 + exact GELU (M=16000, N=4096, K=1024)
    k_tgemm<<<dim3(125, 32), 256, TGEMM_SMEM>>>(pH1, W1, b1, pMid, Ee, MLPn, 1, 1.0f);
    // 12. MLP2 (M=16000, N=1024, K=4096)
    k_tgemm<<<dim3(125, 8), 256, TGEMM_SMEM>>>(pMid, W2, b2, pH2, MLPn, Ee, 2, 1.0f);
    // 13. LN2 -> g_h1 (reuse)
    k_ln<<<Bb * Ss, 256>>>(pH2, g2, be2, pH1);
    // 14. (B,S,E) -> out (B,E,S)
    k_transpose_out<<<dim3(Ee / 32, (Ss + 31) / 32, Bb), tb32>>>(out);
}